// round 14
// baseline (speedup 1.0000x reference)
#include <cuda_runtime.h>
#include <cuda_bf16.h>
#include <mma.h>
#include <cstdint>
#include <cstddef>

using namespace nvcuda;

// Problem constants
#define BB 2
#define LL 1024
#define HH 2048
#define HD 64
#define NQ 32
#define NK 4
#define NPREV 28

// Scratch (device globals)
__device__ float g_Q[(size_t)BB * NQ * LL * HD];
__device__ float g_K[(size_t)BB * NQ * LL * HD];
__device__ float g_V[(size_t)BB * NQ * LL * HD];
__device__ float g_AO[(size_t)BB * LL * (NQ * HD)];

// ---------------------------------------------------------------------------
// Double-buffered TF32 GEMM, BK=16 (R12-proven config). C = A @ W^T.
// MODE 0: plain C1[m*N+n].
// MODE 1: fused QKV. Columns 0-2047 from W1 (Wq) -> C1 (Q scatter);
//         2048-2303 from W2 (Wk) -> C2 (K head NPREV+h);
//         2304-2559 from W3 (Wv) -> C3 (V head NPREV+h).
// ---------------------------------------------------------------------------
#define LDS 20   // 16 + 4 pad floats

template<int BM, int BN, int WARPS_M, int WARPS_N, int MODE>
__global__ void __launch_bounds__(256, 2) gemm_pipe(
    const float* __restrict__ A,  const float* __restrict__ W1,
    const float* __restrict__ W2, const float* __restrict__ W3,
    float* __restrict__ C1, float* __restrict__ C2, float* __restrict__ C3,
    int M, int N, int K)
{
    constexpr int MI  = BM / (16 * WARPS_M);
    constexpr int NJ  = BN / (16 * WARPS_N);
    constexpr int APT = BM * 4 / 256;
    constexpr int BPT = BN * 4 / 256;

    __shared__ __align__(16) float As[2][BM][LDS];
    __shared__ __align__(16) float Bs[2][BN][LDS];

    const int t    = threadIdx.x;
    const int warp = t >> 5;
    const int wm   = warp % WARPS_M;
    const int wn   = warp / WARPS_M;
    const int row0 = blockIdx.y * BM;
    const int col0 = blockIdx.x * BN;

    const float* aptr[APT];
    int ar[APT], ac[APT];
#pragma unroll
    for (int q = 0; q < APT; q++) {
        int f = q * 256 + t;
        ar[q] = f >> 2; ac[q] = (f & 3) * 4;
        aptr[q] = A + (size_t)(row0 + ar[q]) * K + ac[q];
    }
    const float* bptr[BPT];
    int br[BPT], bc[BPT];
#pragma unroll
    for (int q = 0; q < BPT; q++) {
        int f = q * 256 + t;
        br[q] = f >> 2; bc[q] = (f & 3) * 4;
        int rw = col0 + br[q];
        const float* src;
        if (MODE == 1) {
            if (rw < 2048)      src = W1 + (size_t)rw * K;
            else if (rw < 2304) src = W2 + (size_t)(rw - 2048) * K;
            else                src = W3 + (size_t)(rw - 2304) * K;
        } else {
            src = W1 + (size_t)rw * K;
        }
        bptr[q] = src + bc[q];
    }

    wmma::fragment<wmma::accumulator, 16, 16, 8, float> acc[MI][NJ];
#pragma unroll
    for (int i = 0; i < MI; i++)
#pragma unroll
        for (int j = 0; j < NJ; j++) wmma::fill_fragment(acc[i][j], 0.0f);

    float4 ra[APT], rb[BPT];

    auto ldg = [&](int bk) {
#pragma unroll
        for (int q = 0; q < APT; q++) ra[q] = *(const float4*)(aptr[q] + bk);
#pragma unroll
        for (int q = 0; q < BPT; q++) rb[q] = *(const float4*)(bptr[q] + bk);
    };
    auto sts = [&](int buf) {
#pragma unroll
        for (int q = 0; q < APT; q++) {
            float* d = &As[buf][ar[q]][ac[q]];
            d[0] = wmma::__float_to_tf32(ra[q].x);
            d[1] = wmma::__float_to_tf32(ra[q].y);
            d[2] = wmma::__float_to_tf32(ra[q].z);
            d[3] = wmma::__float_to_tf32(ra[q].w);
        }
#pragma unroll
        for (int q = 0; q < BPT; q++) {
            float* d = &Bs[buf][br[q]][bc[q]];
            d[0] = wmma::__float_to_tf32(rb[q].x);
            d[1] = wmma::__float_to_tf32(rb[q].y);
            d[2] = wmma::__float_to_tf32(rb[q].z);
            d[3] = wmma::__float_to_tf32(rb[q].w);
        }
    };
    auto compute = [&](int buf) {
#pragma unroll
        for (int ks = 0; ks < 2; ks++) {
            wmma::fragment<wmma::matrix_a, 16, 16, 8, wmma::precision::tf32,
                           wmma::row_major> af[MI];
#pragma unroll
            for (int i = 0; i < MI; i++)
                wmma::load_matrix_sync(af[i],
                    &As[buf][(wm * MI + i) * 16][ks * 8], LDS);
#pragma unroll
            for (int j = 0; j < NJ; j++) {
                wmma::fragment<wmma::matrix_b, 16, 16, 8, wmma::precision::tf32,
                               wmma::col_major> bf;
                wmma::load_matrix_sync(bf,
                    &Bs[buf][(wn * NJ + j) * 16][ks * 8], LDS);
#pragma unroll
                for (int i = 0; i < MI; i++)
                    wmma::mma_sync(acc[i][j], af[i], bf, acc[i][j]);
            }
        }
    };

    const int nit = K / 16;
    ldg(0);
    sts(0);
    __syncthreads();
    for (int i = 0; i < nit; i++) {
        int buf = i & 1;
        if (i + 1 < nit) ldg((i + 1) * 16);
        compute(buf);
        if (i + 1 < nit) {
            sts(buf ^ 1);
            __syncthreads();
        }
    }

#pragma unroll
    for (int i = 0; i < MI; i++) {
        int m0 = row0 + (wm * MI + i) * 16;
#pragma unroll
        for (int j = 0; j < NJ; j++) {
            int n0 = col0 + (wn * NJ + j) * 16;
            if (MODE == 0) {
                wmma::store_matrix_sync(C1 + (size_t)m0 * N + n0, acc[i][j], N,
                                        wmma::mem_row_major);
            } else {
                int b = m0 >> 10, l = m0 & 1023;
                float* dst;
                if (n0 < 2048) {
                    int h = n0 >> 6, d = n0 & 63;
                    dst = C1 + ((size_t)((b * 32 + h) * 1024 + l)) * 64 + d;
                } else if (n0 < 2304) {
                    int h = (n0 - 2048) >> 6, d = n0 & 63;
                    dst = C2 + ((size_t)((b * 32 + NPREV + h) * 1024 + l)) * 64 + d;
                } else {
                    int h = (n0 - 2304) >> 6, d = n0 & 63;
                    dst = C3 + ((size_t)((b * 32 + NPREV + h) * 1024 + l)) * 64 + d;
                }
                wmma::store_matrix_sync(dst, acc[i][j], 64, wmma::mem_row_major);
            }
        }
    }
}

// ---------------------------------------------------------------------------
// RoPE + cache gather (unchanged)
// ---------------------------------------------------------------------------
__global__ void __launch_bounds__(256) rope_gather_kernel(
    const float* __restrict__ prev_k, const float* __restrict__ prev_v,
    const float* __restrict__ cosp,   const float* __restrict__ sinp)
{
    unsigned t = blockIdx.x * 256u + threadIdx.x;
    int d = t & 31;
    int l = (t >> 5) & 1023;
    int h = (t >> 15) & 31;
    int b = t >> 20;

    float c = cosp[l * 64 + d];
    float s = sinp[l * 64 + d];

    size_t base = ((size_t)(b * 32 + h) * 1024 + l) * 64;

    {
        float* q = g_Q + base;
        float x1 = q[d], x2 = q[d + 32];
        q[d]      = x1 * c - x2 * s;
        q[d + 32] = x2 * c + x1 * s;
    }
    {
        float* k = g_K + base;
        float y1, y2;
        if (h < NPREV) {
            const float* pk = prev_k + ((size_t)(b * NPREV + h) * 1024 + l) * 64;
            y1 = pk[d]; y2 = pk[d + 32];
        } else {
            y1 = k[d]; y2 = k[d + 32];
        }
        k[d]      = y1 * c - y2 * s;
        k[d + 32] = y2 * c + y1 * s;
    }
    if (h < NPREV) {
        const float* pv = prev_v + ((size_t)(b * NPREV + h) * 1024 + l) * 64;
        float* v = g_V + base;
        v[d]      = pv[d];
        v[d + 32] = pv[d + 32];
    }
}

// ---------------------------------------------------------------------------
// Flash attention, tf32 wmma, O resident in accumulator fragments (R13),
// with heavy-tiles-first scheduling (qt reversed vs blockIdx.x).
// ---------------------------------------------------------------------------
#define FLD  68
#define CTLD 20
#define FSM  ((4 * 64 * FLD + 64 * CTLD) * 4)

__global__ void __launch_bounds__(256, 2) flash_wmma(
    const float* __restrict__ Q, const float* __restrict__ K,
    const float* __restrict__ V, float* __restrict__ AO)
{
    extern __shared__ float sm[];
    float* Qs = sm;
    float* Ks = sm + 64 * FLD;
    float* Vs = sm + 2 * 64 * FLD;
    float* Ss = sm + 3 * 64 * FLD;
    float* Ct = sm + 4 * 64 * FLD;

    const int t    = threadIdx.x;
    const int warp = t >> 5;
    const int wm   = warp & 3;
    const int wn   = warp >> 2;
    const int qt   = (int)gridDim.x - 1 - (int)blockIdx.x;  // heavy first
    const int h    = blockIdx.y;
    const int b    = blockIdx.z;
    const int q0   = qt * 64;

    const size_t bh_off = (size_t)(b * 32 + h) * 1024 * 64;
    const float* Qp = Q + bh_off;
    const float* Kp = K + bh_off;
    const float* Vp = V + bh_off;

    float4 rk[4], rv[4];
    int fr[4], fc[4];
#pragma unroll
    for (int q = 0; q < 4; q++) {
        int f = q * 256 + t;
        fr[q] = f >> 4; fc[q] = (f & 15) * 4;
    }

    auto kv_ldg = [&](int j) {
#pragma unroll
        for (int q = 0; q < 4; q++) {
            size_t goff = (size_t)(j * 64 + fr[q]) * 64 + fc[q];
            rk[q] = *(const float4*)(Kp + goff);
            rv[q] = *(const float4*)(Vp + goff);
        }
    };
    auto kv_sts = [&]() {
#pragma unroll
        for (int q = 0; q < 4; q++) {
            float* dk = Ks + fr[q] * FLD + fc[q];
            dk[0] = wmma::__float_to_tf32(rk[q].x);
            dk[1] = wmma::__float_to_tf32(rk[q].y);
            dk[2] = wmma::__float_to_tf32(rk[q].z);
            dk[3] = wmma::__float_to_tf32(rk[q].w);
            float* dv = Vs + fr[q] * FLD + fc[q];
            dv[0] = wmma::__float_to_tf32(rv[q].x);
            dv[1] = wmma::__float_to_tf32(rv[q].y);
            dv[2] = wmma::__float_to_tf32(rv[q].z);
            dv[3] = wmma::__float_to_tf32(rv[q].w);
        }
    };

#pragma unroll
    for (int q = 0; q < 4; q++) {
        float4 v = *(const float4*)(Qp + (size_t)(q0 + fr[q]) * 64 + fc[q]);
        float* dq = Qs + fr[q] * FLD + fc[q];
        dq[0] = wmma::__float_to_tf32(v.x);
        dq[1] = wmma::__float_to_tf32(v.y);
        dq[2] = wmma::__float_to_tf32(v.z);
        dq[3] = wmma::__float_to_tf32(v.w);
    }
    kv_ldg(0);
    kv_sts();
    __syncthreads();

    wmma::fragment<wmma::accumulator, 16, 16, 8, float> oacc[2];
#pragma unroll
    for (int n = 0; n < 2; n++) wmma::fill_fragment(oacc[n], 0.0f);

    const int srow = t >> 2;
    const int scol = (t & 3) * 16;
    float m_r = -1e30f, l_r = 0.0f;

    for (int j = 0; j <= qt; j++) {
        if (j < qt) kv_ldg(j + 1);

        // S = Q @ K^T
        {
            wmma::fragment<wmma::accumulator, 16, 16, 8, float> sacc[2];
#pragma unroll
            for (int n = 0; n < 2; n++) wmma::fill_fragment(sacc[n], 0.0f);
#pragma unroll
            for (int ks = 0; ks < 8; ks++) {
                wmma::fragment<wmma::matrix_a, 16, 16, 8, wmma::precision::tf32,
                               wmma::row_major> af;
                wmma::load_matrix_sync(af, Qs + (wm * 16) * FLD + ks * 8, FLD);
#pragma unroll
                for (int n = 0; n < 2; n++) {
                    wmma::fragment<wmma::matrix_b, 16, 16, 8, wmma::precision::tf32,
                                   wmma::col_major> bf;
                    wmma::load_matrix_sync(bf, Ks + (wn * 32 + n * 16) * FLD + ks * 8, FLD);
                    wmma::mma_sync(sacc[n], af, bf, sacc[n]);
                }
            }
#pragma unroll
            for (int n = 0; n < 2; n++)
                wmma::store_matrix_sync(Ss + (wm * 16) * FLD + wn * 32 + n * 16,
                                        sacc[n], FLD, wmma::mem_row_major);
        }
        __syncthreads();

        // Online softmax (4 threads/row)
        {
            float sv[16];
#pragma unroll
            for (int i4 = 0; i4 < 4; i4++) {
                float4 v = *(const float4*)(Ss + srow * FLD + scol + i4 * 4);
                sv[i4 * 4 + 0] = v.x * 0.125f;
                sv[i4 * 4 + 1] = v.y * 0.125f;
                sv[i4 * 4 + 2] = v.z * 0.125f;
                sv[i4 * 4 + 3] = v.w * 0.125f;
            }
            if (j == qt) {
#pragma unroll
                for (int i = 0; i < 16; i++)
                    if (scol + i > srow) sv[i] = -1e30f;
            }
            float mx = sv[0];
#pragma unroll
            for (int i = 1; i < 16; i++) mx = fmaxf(mx, sv[i]);
            mx = fmaxf(mx, __shfl_xor_sync(0xffffffffu, mx, 1));
            mx = fmaxf(mx, __shfl_xor_sync(0xffffffffu, mx, 2));
            float mnew = fmaxf(m_r, mx);
            float corr = __expf(m_r - mnew);
            float rs = 0.0f;
#pragma unroll
            for (int i = 0; i < 16; i++) {
                sv[i] = __expf(sv[i] - mnew);
                rs += sv[i];
            }
            rs += __shfl_xor_sync(0xffffffffu, rs, 1);
            rs += __shfl_xor_sync(0xffffffffu, rs, 2);
            l_r = l_r * corr + rs;
            m_r = mnew;
#pragma unroll
            for (int i4 = 0; i4 < 4; i4++) {
                float4 p;
                p.x = wmma::__float_to_tf32(sv[i4 * 4 + 0]);
                p.y = wmma::__float_to_tf32(sv[i4 * 4 + 1]);
                p.z = wmma::__float_to_tf32(sv[i4 * 4 + 2]);
                p.w = wmma::__float_to_tf32(sv[i4 * 4 + 3]);
                *(float4*)(Ss + srow * FLD + scol + i4 * 4) = p;
            }
            float* cd = Ct + srow * CTLD + (t & 3) * 4;
            cd[0] = corr; cd[1] = corr; cd[2] = corr; cd[3] = corr;
        }
        __syncthreads();

        // O *= corr; O += P @ V
        {
            wmma::fragment<wmma::accumulator, 16, 16, 8, float> cf;
            wmma::load_matrix_sync(cf, Ct + (wm * 16) * CTLD, CTLD,
                                   wmma::mem_row_major);
#pragma unroll
            for (int n = 0; n < 2; n++)
#pragma unroll
                for (int e = 0; e < cf.num_elements; e++)
                    oacc[n].x[e] *= cf.x[e];

#pragma unroll
            for (int ks = 0; ks < 8; ks++) {
                wmma::fragment<wmma::matrix_a, 16, 16, 8, wmma::precision::tf32,
                               wmma::row_major> af;
                wmma::load_matrix_sync(af, Ss + (wm * 16) * FLD + ks * 8, FLD);
#pragma unroll
                for (int n = 0; n < 2; n++) {
                    wmma::fragment<wmma::matrix_b, 16, 16, 8, wmma::precision::tf32,
                                   wmma::row_major> bf;
                    wmma::load_matrix_sync(bf, Vs + (ks * 8) * FLD + wn * 32 + n * 16, FLD);
                    wmma::mma_sync(oacc[n], af, bf, oacc[n]);
                }
            }
        }
        __syncthreads();

        if (j < qt) {
            kv_sts();
            __syncthreads();
        }
    }

#pragma unroll
    for (int n = 0; n < 2; n++)
        wmma::store_matrix_sync(Ss + (wm * 16) * FLD + wn * 32 + n * 16,
                                oacc[n], FLD, wmma::mem_row_major);
    __syncthreads();
    {
        float rl = 1.0f / l_r;
        size_t row = (size_t)b * 1024 + (q0 + srow);
        float* dst = AO + row * 2048 + h * 64 + scol;
#pragma unroll
        for (int i4 = 0; i4 < 4; i4++) {
            float4 o = *(const float4*)(Ss + srow * FLD + scol + i4 * 4);
            o.x *= rl; o.y *= rl; o.z *= rl; o.w *= rl;
            *(float4*)(dst + i4 * 4) = o;
        }
    }
}

// ---------------------------------------------------------------------------
// Launch
// ---------------------------------------------------------------------------
extern "C" void kernel_launch(void* const* d_in, const int* in_sizes, int n_in,
                              void* d_out, int out_size)
{
    const float* hs   = (const float*)d_in[0];
    const float* pk   = (const float*)d_in[1];
    const float* pv   = (const float*)d_in[2];
    const float* Wq   = (const float*)d_in[3];
    const float* Wk   = (const float*)d_in[4];
    const float* Wv   = (const float*)d_in[5];
    const float* Wo   = (const float*)d_in[6];
    const float* cosp = (const float*)d_in[7];
    const float* sinp = (const float*)d_in[8];
    float* out = (float*)d_out;

    float *Qb, *Kb, *Vb, *AO;
    cudaGetSymbolAddress((void**)&Qb, g_Q);
    cudaGetSymbolAddress((void**)&Kb, g_K);
    cudaGetSymbolAddress((void**)&Vb, g_V);
    cudaGetSymbolAddress((void**)&AO, g_AO);

    cudaFuncSetAttribute(flash_wmma,
                         cudaFuncAttributeMaxDynamicSharedMemorySize, FSM);

    // Fused Q+K+V projection: one launch, N=2560, 320 blocks
    gemm_pipe<128, 128, 4, 2, 1><<<dim3(20, 16), 256>>>(
        hs, Wq, Wk, Wv, Qb, Kb, Vb, 2048, 2560, 2048);

    // Cache gather + RoPE
    rope_gather_kernel<<<8192, 256>>>(pk, pv, cosp, sinp);

    // Causal flash attention -> g_AO [B, L, 2048]
    flash_wmma<<<dim3(16, 32, 2), 256, FSM>>>(Qb, Kb, Vb, AO);

    // Output projection
    gemm_pipe<128, 128, 4, 2, 0><<<dim3(16, 16), 256>>>(
        AO, Wo, nullptr, nullptr, out, nullptr, nullptr, 2048, 2048, 2048);
}

// round 15
// speedup vs baseline: 1.0628x; 1.0628x over previous
#include <cuda_runtime.h>
#include <cuda_bf16.h>
#include <mma.h>
#include <cstdint>
#include <cstddef>

using namespace nvcuda;

// Problem constants
#define BB 2
#define LL 1024
#define HH 2048
#define HD 64
#define NQ 32
#define NK 4
#define NPREV 28

// Scratch (device globals)
__device__ float g_Q[(size_t)BB * NQ * LL * HD];
__device__ float g_K[(size_t)BB * NQ * LL * HD];
__device__ float g_V[(size_t)BB * NQ * LL * HD];
__device__ float g_AO[(size_t)BB * LL * (NQ * HD)];
// Pre-converted (tf32-rounded) GEMM operands
__device__ float g_hsT[(size_t)BB * LL * HH];
__device__ float g_WqT[(size_t)NQ * HD * HH];
__device__ float g_WkT[(size_t)NK * HD * HH];
__device__ float g_WvT[(size_t)NK * HD * HH];
__device__ float g_WoT[(size_t)HH * NQ * HD];

// ---------------------------------------------------------------------------
// cp.async helpers
// ---------------------------------------------------------------------------
__device__ __forceinline__ void cp_async16(uint32_t smem, const void* gmem) {
    asm volatile("cp.async.cg.shared.global [%0], [%1], 16;\n"
                 :: "r"(smem), "l"(gmem));
}
__device__ __forceinline__ void cp_commit() {
    asm volatile("cp.async.commit_group;\n" ::: "memory");
}
template<int N> __device__ __forceinline__ void cp_wait() {
    asm volatile("cp.async.wait_group %0;\n" :: "n"(N) : "memory");
}

// ---------------------------------------------------------------------------
// tf32 rounding convert kernel (grid-stride, float4)
// ---------------------------------------------------------------------------
__global__ void cvt_tf32(const float4* __restrict__ src, float4* __restrict__ dst,
                         int n4)
{
    int i = blockIdx.x * blockDim.x + threadIdx.x;
    int stride = gridDim.x * blockDim.x;
    for (; i < n4; i += stride) {
        float4 v = src[i];
        v.x = wmma::__float_to_tf32(v.x);
        v.y = wmma::__float_to_tf32(v.y);
        v.z = wmma::__float_to_tf32(v.z);
        v.w = wmma::__float_to_tf32(v.w);
        dst[i] = v;
    }
}

// ---------------------------------------------------------------------------
// 4-stage cp.async TF32 GEMM: C = A @ W^T. Inputs pre-rounded to tf32.
// MODE 0: plain C1. MODE 1: Q scatter (plain stores; rope rounds later).
// MODE 2: fused KV: col<256 from W1 -> C1 (K head NPREV+h, plain),
//                   col>=256 from W2 -> C2 (V head NPREV+h-4, ROUNDED stores).
// ---------------------------------------------------------------------------
#define LDS 20   // 16 + 4 pad floats; rows 80B = 5x16B (16B-aligned)

template<int BM, int BN, int WM, int WN, int MODE>
__global__ void __launch_bounds__(256, 2) gemm_ca(
    const float* __restrict__ A, const float* __restrict__ W1,
    const float* __restrict__ W2, float* __restrict__ C1,
    float* __restrict__ C2, int M, int N, int K)
{
    constexpr int S    = 4;
    constexpr int MI   = BM / (16 * WM);
    constexpr int NJ   = BN / (16 * WN);
    constexpr int APT  = BM / 64;          // float4 per thread per stage (A)
    constexpr int BPT  = BN / 64;
    constexpr int ABUF = BM * LDS;         // floats per A stage
    constexpr int BBUF = BN * LDS;

    extern __shared__ float gsm[];
    float* As = gsm;                 // [S][BM][LDS]
    float* Bs = gsm + S * ABUF;      // [S][BN][LDS]

    const int t    = threadIdx.x;
    const int warp = t >> 5;
    const int wm   = warp % WM;
    const int wn   = warp / WM;
    const int row0 = blockIdx.y * BM;
    const int col0 = blockIdx.x * BN;

    const float* aptr[APT];
    uint32_t aoff[APT];
#pragma unroll
    for (int q = 0; q < APT; q++) {
        int f = q * 256 + t;
        int r = f >> 2, c = (f & 3) * 4;
        aptr[q] = A + (size_t)(row0 + r) * K + c;
        aoff[q] = (uint32_t)__cvta_generic_to_shared(&As[r * LDS + c]);
    }
    const float* bptr[BPT];
    uint32_t boff[BPT];
#pragma unroll
    for (int q = 0; q < BPT; q++) {
        int f = q * 256 + t;
        int r = f >> 2, c = (f & 3) * 4;
        int rw = col0 + r;
        const float* src;
        if (MODE == 2) src = (rw < 256) ? (W1 + (size_t)rw * K)
                                        : (W2 + (size_t)(rw - 256) * K);
        else           src = W1 + (size_t)rw * K;
        bptr[q] = src + c;
        boff[q] = (uint32_t)__cvta_generic_to_shared(&Bs[r * LDS + c]);
    }

    wmma::fragment<wmma::accumulator, 16, 16, 8, float> acc[MI][NJ];
#pragma unroll
    for (int i = 0; i < MI; i++)
#pragma unroll
        for (int j = 0; j < NJ; j++) wmma::fill_fragment(acc[i][j], 0.0f);

    auto issue = [&](int chunk) {
        int st = chunk & (S - 1);
        int bk = chunk * 16;
#pragma unroll
        for (int q = 0; q < APT; q++)
            cp_async16(aoff[q] + st * ABUF * 4, aptr[q] + bk);
#pragma unroll
        for (int q = 0; q < BPT; q++)
            cp_async16(boff[q] + st * BBUF * 4, bptr[q] + bk);
    };
    auto compute = [&](int st) {
        const float* Ab = As + st * ABUF;
        const float* Bb = Bs + st * BBUF;
#pragma unroll
        for (int ks = 0; ks < 2; ks++) {
            wmma::fragment<wmma::matrix_a, 16, 16, 8, wmma::precision::tf32,
                           wmma::row_major> af[MI];
#pragma unroll
            for (int i = 0; i < MI; i++)
                wmma::load_matrix_sync(af[i],
                    Ab + (wm * MI + i) * 16 * LDS + ks * 8, LDS);
#pragma unroll
            for (int j = 0; j < NJ; j++) {
                wmma::fragment<wmma::matrix_b, 16, 16, 8, wmma::precision::tf32,
                               wmma::col_major> bf;
                wmma::load_matrix_sync(bf,
                    Bb + (wn * NJ + j) * 16 * LDS + ks * 8, LDS);
#pragma unroll
                for (int i = 0; i < MI; i++)
                    wmma::mma_sync(acc[i][j], af[i], bf, acc[i][j]);
            }
        }
    };

    const int nit = K / 16;
    issue(0); cp_commit();
    issue(1); cp_commit();
    issue(2); cp_commit();
    for (int i = 0; i < nit; i++) {
        cp_wait<S - 2>();
        __syncthreads();
        if (i + S - 1 < nit) issue(i + S - 1);
        cp_commit();
        compute(i & (S - 1));
    }

    // Epilogue
#pragma unroll
    for (int i = 0; i < MI; i++) {
        int m0 = row0 + (wm * MI + i) * 16;
#pragma unroll
        for (int j = 0; j < NJ; j++) {
            int n0 = col0 + (wn * NJ + j) * 16;
            if (MODE == 0) {
                wmma::store_matrix_sync(C1 + (size_t)m0 * N + n0, acc[i][j], N,
                                        wmma::mem_row_major);
            } else if (MODE == 1) {
                int b = m0 >> 10, l = m0 & 1023;
                int h = n0 >> 6,  d = n0 & 63;
                float* dst = C1 + ((size_t)((b * 32 + h) * 1024 + l)) * 64 + d;
                wmma::store_matrix_sync(dst, acc[i][j], 64, wmma::mem_row_major);
            } else {
                int b = m0 >> 10, l = m0 & 1023;
                int h = n0 >> 6,  d = n0 & 63;
                if (h < 4) {  // K: rope re-rounds later
                    float* dst = C1 + ((size_t)((b * 32 + NPREV + h) * 1024 + l)) * 64 + d;
                    wmma::store_matrix_sync(dst, acc[i][j], 64, wmma::mem_row_major);
                } else {      // V heads 28-31: round here (never touched again)
#pragma unroll
                    for (int e = 0; e < acc[i][j].num_elements; e++)
                        acc[i][j].x[e] = wmma::__float_to_tf32(acc[i][j].x[e]);
                    float* dst = C2 + ((size_t)((b * 32 + NPREV + h - 4) * 1024 + l)) * 64 + d;
                    wmma::store_matrix_sync(dst, acc[i][j], 64, wmma::mem_row_major);
                }
            }
        }
    }
}

// ---------------------------------------------------------------------------
// RoPE + cache gather. Stores tf32-rounded (flash consumes raw).
// ---------------------------------------------------------------------------
__global__ void __launch_bounds__(256) rope_gather_kernel(
    const float* __restrict__ prev_k, const float* __restrict__ prev_v,
    const float* __restrict__ cosp,   const float* __restrict__ sinp)
{
    unsigned t = blockIdx.x * 256u + threadIdx.x;
    int d = t & 31;
    int l = (t >> 5) & 1023;
    int h = (t >> 15) & 31;
    int b = t >> 20;

    float c = cosp[l * 64 + d];
    float s = sinp[l * 64 + d];

    size_t base = ((size_t)(b * 32 + h) * 1024 + l) * 64;

    {
        float* q = g_Q + base;
        float x1 = q[d], x2 = q[d + 32];
        q[d]      = wmma::__float_to_tf32(x1 * c - x2 * s);
        q[d + 32] = wmma::__float_to_tf32(x2 * c + x1 * s);
    }
    {
        float* k = g_K + base;
        float y1, y2;
        if (h < NPREV) {
            const float* pk = prev_k + ((size_t)(b * NPREV + h) * 1024 + l) * 64;
            y1 = pk[d]; y2 = pk[d + 32];
        } else {
            y1 = k[d]; y2 = k[d + 32];
        }
        k[d]      = wmma::__float_to_tf32(y1 * c - y2 * s);
        k[d + 32] = wmma::__float_to_tf32(y2 * c + y1 * s);
    }
    if (h < NPREV) {
        const float* pv = prev_v + ((size_t)(b * NPREV + h) * 1024 + l) * 64;
        float* v = g_V + base;
        v[d]      = wmma::__float_to_tf32(pv[d]);
        v[d + 32] = wmma::__float_to_tf32(pv[d + 32]);
    }
}

// ---------------------------------------------------------------------------
// Flash attention (R13 fragment-O version; inputs pre-rounded so smem fill is
// a plain copy; AO stores tf32-rounded for the cp.async Wo GEMM).
// ---------------------------------------------------------------------------
#define FLD  68
#define CTLD 20
#define FSM  ((4 * 64 * FLD + 64 * CTLD) * 4)

__global__ void __launch_bounds__(256, 2) flash_wmma(
    const float* __restrict__ Q, const float* __restrict__ K,
    const float* __restrict__ V, float* __restrict__ AO)
{
    extern __shared__ float sm[];
    float* Qs = sm;
    float* Ks = sm + 64 * FLD;
    float* Vs = sm + 2 * 64 * FLD;
    float* Ss = sm + 3 * 64 * FLD;
    float* Ct = sm + 4 * 64 * FLD;

    const int t    = threadIdx.x;
    const int warp = t >> 5;
    const int wm   = warp & 3;
    const int wn   = warp >> 2;
    const int qt   = blockIdx.x;
    const int h    = blockIdx.y;
    const int b    = blockIdx.z;
    const int q0   = qt * 64;

    const size_t bh_off = (size_t)(b * 32 + h) * 1024 * 64;
    const float* Qp = Q + bh_off;
    const float* Kp = K + bh_off;
    const float* Vp = V + bh_off;

    float4 rk[4], rv[4];
    int fr[4], fc[4];
#pragma unroll
    for (int q = 0; q < 4; q++) {
        int f = q * 256 + t;
        fr[q] = f >> 4; fc[q] = (f & 15) * 4;
    }

    auto kv_ldg = [&](int j) {
#pragma unroll
        for (int q = 0; q < 4; q++) {
            size_t goff = (size_t)(j * 64 + fr[q]) * 64 + fc[q];
            rk[q] = *(const float4*)(Kp + goff);
            rv[q] = *(const float4*)(Vp + goff);
        }
    };
    auto kv_sts = [&]() {
#pragma unroll
        for (int q = 0; q < 4; q++) {
            *(float4*)(Ks + fr[q] * FLD + fc[q]) = rk[q];
            *(float4*)(Vs + fr[q] * FLD + fc[q]) = rv[q];
        }
    };

#pragma unroll
    for (int q = 0; q < 4; q++) {
        float4 v = *(const float4*)(Qp + (size_t)(q0 + fr[q]) * 64 + fc[q]);
        *(float4*)(Qs + fr[q] * FLD + fc[q]) = v;
    }
    kv_ldg(0);
    kv_sts();
    __syncthreads();

    wmma::fragment<wmma::accumulator, 16, 16, 8, float> oacc[2];
#pragma unroll
    for (int n = 0; n < 2; n++) wmma::fill_fragment(oacc[n], 0.0f);

    const int srow = t >> 2;
    const int scol = (t & 3) * 16;
    float m_r = -1e30f, l_r = 0.0f;

    for (int j = 0; j <= qt; j++) {
        if (j < qt) kv_ldg(j + 1);

        // S = Q @ K^T
        {
            wmma::fragment<wmma::accumulator, 16, 16, 8, float> sacc[2];
#pragma unroll
            for (int n = 0; n < 2; n++) wmma::fill_fragment(sacc[n], 0.0f);
#pragma unroll
            for (int ks = 0; ks < 8; ks++) {
                wmma::fragment<wmma::matrix_a, 16, 16, 8, wmma::precision::tf32,
                               wmma::row_major> af;
                wmma::load_matrix_sync(af, Qs + (wm * 16) * FLD + ks * 8, FLD);
#pragma unroll
                for (int n = 0; n < 2; n++) {
                    wmma::fragment<wmma::matrix_b, 16, 16, 8, wmma::precision::tf32,
                                   wmma::col_major> bf;
                    wmma::load_matrix_sync(bf, Ks + (wn * 32 + n * 16) * FLD + ks * 8, FLD);
                    wmma::mma_sync(sacc[n], af, bf, sacc[n]);
                }
            }
#pragma unroll
            for (int n = 0; n < 2; n++)
                wmma::store_matrix_sync(Ss + (wm * 16) * FLD + wn * 32 + n * 16,
                                        sacc[n], FLD, wmma::mem_row_major);
        }
        __syncthreads();

        // Online softmax (4 threads/row)
        {
            float sv[16];
#pragma unroll
            for (int i4 = 0; i4 < 4; i4++) {
                float4 v = *(const float4*)(Ss + srow * FLD + scol + i4 * 4);
                sv[i4 * 4 + 0] = v.x * 0.125f;
                sv[i4 * 4 + 1] = v.y * 0.125f;
                sv[i4 * 4 + 2] = v.z * 0.125f;
                sv[i4 * 4 + 3] = v.w * 0.125f;
            }
            if (j == qt) {
#pragma unroll
                for (int i = 0; i < 16; i++)
                    if (scol + i > srow) sv[i] = -1e30f;
            }
            float mx = sv[0];
#pragma unroll
            for (int i = 1; i < 16; i++) mx = fmaxf(mx, sv[i]);
            mx = fmaxf(mx, __shfl_xor_sync(0xffffffffu, mx, 1));
            mx = fmaxf(mx, __shfl_xor_sync(0xffffffffu, mx, 2));
            float mnew = fmaxf(m_r, mx);
            float corr = __expf(m_r - mnew);
            float rs = 0.0f;
#pragma unroll
            for (int i = 0; i < 16; i++) {
                sv[i] = __expf(sv[i] - mnew);
                rs += sv[i];
            }
            rs += __shfl_xor_sync(0xffffffffu, rs, 1);
            rs += __shfl_xor_sync(0xffffffffu, rs, 2);
            l_r = l_r * corr + rs;
            m_r = mnew;
#pragma unroll
            for (int i4 = 0; i4 < 4; i4++) {
                float4 p;
                p.x = wmma::__float_to_tf32(sv[i4 * 4 + 0]);
                p.y = wmma::__float_to_tf32(sv[i4 * 4 + 1]);
                p.z = wmma::__float_to_tf32(sv[i4 * 4 + 2]);
                p.w = wmma::__float_to_tf32(sv[i4 * 4 + 3]);
                *(float4*)(Ss + srow * FLD + scol + i4 * 4) = p;
            }
            float* cd = Ct + srow * CTLD + (t & 3) * 4;
            cd[0] = corr; cd[1] = corr; cd[2] = corr; cd[3] = corr;
        }
        __syncthreads();

        // O *= corr; O += P @ V
        {
            wmma::fragment<wmma::accumulator, 16, 16, 8, float> cf;
            wmma::load_matrix_sync(cf, Ct + (wm * 16) * CTLD, CTLD,
                                   wmma::mem_row_major);
#pragma unroll
            for (int n = 0; n < 2; n++)
#pragma unroll
                for (int e = 0; e < cf.num_elements; e++)
                    oacc[n].x[e] *= cf.x[e];

#pragma unroll
            for (int ks = 0; ks < 8; ks++) {
                wmma::fragment<wmma::matrix_a, 16, 16, 8, wmma::precision::tf32,
                               wmma::row_major> af;
                wmma::load_matrix_sync(af, Ss + (wm * 16) * FLD + ks * 8, FLD);
#pragma unroll
                for (int n = 0; n < 2; n++) {
                    wmma::fragment<wmma::matrix_b, 16, 16, 8, wmma::precision::tf32,
                                   wmma::row_major> bf;
                    wmma::load_matrix_sync(bf, Vs + (ks * 8) * FLD + wn * 32 + n * 16, FLD);
                    wmma::mma_sync(oacc[n], af, bf, oacc[n]);
                }
            }
        }
        __syncthreads();

        if (j < qt) {
            kv_sts();
            __syncthreads();
        }
    }

#pragma unroll
    for (int n = 0; n < 2; n++)
        wmma::store_matrix_sync(Ss + (wm * 16) * FLD + wn * 32 + n * 16,
                                oacc[n], FLD, wmma::mem_row_major);
    __syncthreads();
    {
        float rl = 1.0f / l_r;
        size_t row = (size_t)b * 1024 + (q0 + srow);
        float* dst = AO + row * 2048 + h * 64 + scol;
#pragma unroll
        for (int i4 = 0; i4 < 4; i4++) {
            float4 o = *(const float4*)(Ss + srow * FLD + scol + i4 * 4);
            o.x = wmma::__float_to_tf32(o.x * rl);
            o.y = wmma::__float_to_tf32(o.y * rl);
            o.z = wmma::__float_to_tf32(o.z * rl);
            o.w = wmma::__float_to_tf32(o.w * rl);
            *(float4*)(dst + i4 * 4) = o;
        }
    }
}

// ---------------------------------------------------------------------------
// Launch
// ---------------------------------------------------------------------------
extern "C" void kernel_launch(void* const* d_in, const int* in_sizes, int n_in,
                              void* d_out, int out_size)
{
    const float* hs   = (const float*)d_in[0];
    const float* pk   = (const float*)d_in[1];
    const float* pv   = (const float*)d_in[2];
    const float* Wq   = (const float*)d_in[3];
    const float* Wk   = (const float*)d_in[4];
    const float* Wv   = (const float*)d_in[5];
    const float* Wo   = (const float*)d_in[6];
    const float* cosp = (const float*)d_in[7];
    const float* sinp = (const float*)d_in[8];
    float* out = (float*)d_out;

    float *Qb, *Kb, *Vb, *AO, *hsT, *WqT, *WkT, *WvT, *WoT;
    cudaGetSymbolAddress((void**)&Qb,  g_Q);
    cudaGetSymbolAddress((void**)&Kb,  g_K);
    cudaGetSymbolAddress((void**)&Vb,  g_V);
    cudaGetSymbolAddress((void**)&AO,  g_AO);
    cudaGetSymbolAddress((void**)&hsT, g_hsT);
    cudaGetSymbolAddress((void**)&WqT, g_WqT);
    cudaGetSymbolAddress((void**)&WkT, g_WkT);
    cudaGetSymbolAddress((void**)&WvT, g_WvT);
    cudaGetSymbolAddress((void**)&WoT, g_WoT);

    const int smem_g128 = 4 * (128 + 128) * LDS * 4;  // 81920
    const int smem_g64  = 4 * (64 + 128) * LDS * 4;   // 61440

    cudaFuncSetAttribute((const void*)gemm_ca<128, 128, 4, 2, 1>,
                         cudaFuncAttributeMaxDynamicSharedMemorySize, smem_g128);
    cudaFuncSetAttribute((const void*)gemm_ca<128, 128, 4, 2, 0>,
                         cudaFuncAttributeMaxDynamicSharedMemorySize, smem_g128);
    cudaFuncSetAttribute((const void*)gemm_ca<64, 128, 2, 4, 2>,
                         cudaFuncAttributeMaxDynamicSharedMemorySize, smem_g64);
    cudaFuncSetAttribute(flash_wmma,
                         cudaFuncAttributeMaxDynamicSharedMemorySize, FSM);

    // Pre-convert GEMM operands to tf32-rounded fp32 (RN, one conversion each)
    const int NE_HS = BB * LL * HH / 4;       // 1M float4
    const int NE_WQ = NQ * HD * HH / 4;       // 1M
    const int NE_WK = NK * HD * HH / 4;       // 128K
    const int NE_WO = HH * NQ * HD / 4;       // 1M
    cvt_tf32<<<2048, 256>>>((const float4*)hs, (float4*)hsT, NE_HS);
    cvt_tf32<<<2048, 256>>>((const float4*)Wq, (float4*)WqT, NE_WQ);
    cvt_tf32<<<512,  256>>>((const float4*)Wk, (float4*)WkT, NE_WK);
    cvt_tf32<<<512,  256>>>((const float4*)Wv, (float4*)WvT, NE_WK);
    cvt_tf32<<<2048, 256>>>((const float4*)Wo, (float4*)WoT, NE_WO);

    // Q projection (256 blocks, one wave)
    gemm_ca<128, 128, 4, 2, 1><<<dim3(16, 16), 256, smem_g128>>>(
        hsT, WqT, nullptr, Qb, nullptr, 2048, 2048, 2048);
    // Fused K+V projection (128 blocks)
    gemm_ca<64, 128, 2, 4, 2><<<dim3(4, 32), 256, smem_g64>>>(
        hsT, WkT, WvT, Kb, Vb, 2048, 512, 2048);

    // Cache gather + RoPE (tf32-rounded stores)
    rope_gather_kernel<<<8192, 256>>>(pk, pv, cosp, sinp);

    // Causal flash attention -> g_AO (tf32-rounded)
    flash_wmma<<<dim3(16, 32, 2), 256, FSM>>>(Qb, Kb, Vb, AO);

    // Output projection (256 blocks, one wave)
    gemm_ca<128, 128, 4, 2, 0><<<dim3(16, 16), 256, smem_g128>>>(
        AO, WoT, nullptr, out, nullptr, 2048, 2048, 2048);
}